// round 1
// baseline (speedup 1.0000x reference)
#include <cuda_runtime.h>
#include <cstdint>

// Problem constants
#define BATCH 16
#define C     384
#define C3    1152
#define HW    4096
#define HH    64
#define NH    8
#define D     48          // per-head channels
#define QK    768         // q+k channel count per batch

// Scratch (static __device__ allocations — permitted)
__device__ float g_qkv[(size_t)BATCH * C3 * HW];   // 302 MB
__device__ float g_dw [(size_t)BATCH * C3 * HW];   // 302 MB
__device__ float g_inv[BATCH * QK];                // inverse L2 norms for q,k channels
__device__ float g_attn[BATCH * NH * D * D];       // softmaxed attention (small)
__device__ float g_av [(size_t)BATCH * C * HW];    // attn @ v, reshaped (b,c,hw)

// ---------------------------------------------------------------------------
// Generic batched SGEMM: C[b] = W (MxK, row-major) @ X[b] (KxN, row-major)
// BM=BN=128, BK=16, 256 threads, 8x8 per-thread microtile.
// All dims here are multiples of the tile sizes, so no edge guards.
// ---------------------------------------------------------------------------
__global__ __launch_bounds__(256, 2)
void gemm128_kernel(const float* __restrict__ W, const float* __restrict__ X,
                    float* __restrict__ Cout, int M, int N, int K)
{
    const int BM = 128, BN = 128, BK = 16;
    int b = blockIdx.z;
    const float* Xb = X + (size_t)b * K * N;
    float*       Cb = Cout + (size_t)b * M * N;

    __shared__ float As[BK][BM];
    __shared__ float Bs[BK][BN];

    int tid  = threadIdx.x;
    int row0 = blockIdx.y * BM;
    int col0 = blockIdx.x * BN;
    int tr   = (tid / 16) * 8;
    int tc   = (tid % 16) * 8;

    float acc[8][8];
    #pragma unroll
    for (int i = 0; i < 8; i++)
        #pragma unroll
        for (int j = 0; j < 8; j++) acc[i][j] = 0.f;

    for (int k0 = 0; k0 < K; k0 += BK) {
        // Load A tile (BM x BK) transposed into As[k][m]
        #pragma unroll
        for (int l = tid; l < BM * BK; l += 256) {
            int m = l >> 4, k = l & 15;
            As[k][m] = W[(size_t)(row0 + m) * K + k0 + k];
        }
        // Load B tile (BK x BN) into Bs[k][n]  (fully coalesced)
        #pragma unroll
        for (int l = tid; l < BK * BN; l += 256) {
            int k = l >> 7, n = l & 127;
            Bs[k][n] = Xb[(size_t)(k0 + k) * N + col0 + n];
        }
        __syncthreads();

        #pragma unroll
        for (int kk = 0; kk < BK; kk++) {
            float a[8], bb[8];
            #pragma unroll
            for (int i = 0; i < 8; i++) a[i] = As[kk][tr + i];
            #pragma unroll
            for (int j = 0; j < 8; j++) bb[j] = Bs[kk][tc + j];
            #pragma unroll
            for (int i = 0; i < 8; i++)
                #pragma unroll
                for (int j = 0; j < 8; j++)
                    acc[i][j] += a[i] * bb[j];
        }
        __syncthreads();
    }

    #pragma unroll
    for (int i = 0; i < 8; i++) {
        float* crow = &Cb[(size_t)(row0 + tr + i) * N + col0 + tc];
        #pragma unroll
        for (int j = 0; j < 8; j += 4) {
            float4 v = make_float4(acc[i][j], acc[i][j+1], acc[i][j+2], acc[i][j+3]);
            *reinterpret_cast<float4*>(crow + j) = v;
        }
    }
}

// ---------------------------------------------------------------------------
// Depthwise 3x3 conv, SAME (zero) padding. One block per (b, channel) plane.
// ---------------------------------------------------------------------------
__global__ __launch_bounds__(256)
void dwconv_kernel(const float* __restrict__ in, const float* __restrict__ wdw,
                   float* __restrict__ out)
{
    int plane = blockIdx.x;                 // b*C3 + ch
    int ch    = plane % C3;
    const float* ip = in  + (size_t)plane * HW;
    float*       op = out + (size_t)plane * HW;

    __shared__ float tile[66][66];
    for (int l = threadIdx.x; l < 66 * 66; l += 256) {
        int y = l / 66 - 1, x = l % 66 - 1;
        tile[l / 66][l % 66] =
            (y >= 0 && y < HH && x >= 0 && x < HH) ? ip[y * HH + x] : 0.f;
    }
    __syncthreads();

    float w[9];
    #pragma unroll
    for (int i = 0; i < 9; i++) w[i] = wdw[ch * 9 + i];

    for (int l = threadIdx.x; l < HW; l += 256) {
        int y = l >> 6, x = l & 63;
        float s = 0.f;
        #pragma unroll
        for (int dy = 0; dy < 3; dy++)
            #pragma unroll
            for (int dx = 0; dx < 3; dx++)
                s += w[dy * 3 + dx] * tile[y + dy][x + dx];
        op[l] = s;
    }
}

// ---------------------------------------------------------------------------
// Per-channel inverse L2 norm over hw for the q and k channel blocks.
// One block per (b, channel-in-[0,768)).
// ---------------------------------------------------------------------------
__global__ __launch_bounds__(256)
void norm_kernel(const float* __restrict__ dw, float* __restrict__ inv)
{
    int bi = blockIdx.x;                    // b*768 + i ; i<384 => q, else k
    int b  = bi / QK;
    int i  = bi % QK;
    const float* p = dw + ((size_t)b * C3 + i) * HW;

    float s = 0.f;
    for (int l = threadIdx.x; l < HW; l += 256) {
        float v = p[l];
        s += v * v;
    }
    // reduce within warp then across warps
    #pragma unroll
    for (int o = 16; o > 0; o >>= 1) s += __shfl_down_sync(0xffffffffu, s, o);
    __shared__ float ws[8];
    if ((threadIdx.x & 31) == 0) ws[threadIdx.x >> 5] = s;
    __syncthreads();
    if (threadIdx.x == 0) {
        float t = 0.f;
        #pragma unroll
        for (int k = 0; k < 8; k++) t += ws[k];
        float n = sqrtf(t);
        inv[bi] = 1.f / fmaxf(n, 1e-12f);
    }
}

// ---------------------------------------------------------------------------
// Scores (48x48, K=4096) with folded normalization + temperature, then
// row softmax. One block per (b, head). 256 threads (16x16), 3x3 microtile.
// ---------------------------------------------------------------------------
__global__ __launch_bounds__(256)
void scores_softmax_kernel(const float* __restrict__ dw,
                           const float* __restrict__ inv,
                           const float* __restrict__ temp,
                           float* __restrict__ attn)
{
    int bh = blockIdx.x;                    // b*8 + h
    int b  = bh / NH;
    int h  = bh % NH;
    const float* qbase = dw + ((size_t)b * C3 +       h * D) * HW;
    const float* kbase = dw + ((size_t)b * C3 + C   + h * D) * HW;

    __shared__ float qs[D][65];
    __shared__ float ks[D][65];
    __shared__ float S[D][49];

    int tid = threadIdx.x;
    int tr  = tid / 16;     // 0..15 -> rows tr*3..tr*3+2
    int tc  = tid % 16;

    float acc[3][3];
    #pragma unroll
    for (int i = 0; i < 3; i++)
        #pragma unroll
        for (int j = 0; j < 3; j++) acc[i][j] = 0.f;

    for (int n0 = 0; n0 < HW; n0 += 64) {
        for (int l = tid; l < D * 64; l += 256) {
            int r = l >> 6, c = l & 63;
            qs[r][c] = qbase[(size_t)r * HW + n0 + c];
            ks[r][c] = kbase[(size_t)r * HW + n0 + c];
        }
        __syncthreads();
        #pragma unroll 8
        for (int n = 0; n < 64; n++) {
            float qr[3], kr[3];
            #pragma unroll
            for (int i = 0; i < 3; i++) qr[i] = qs[tr * 3 + i][n];
            #pragma unroll
            for (int j = 0; j < 3; j++) kr[j] = ks[tc * 3 + j][n];
            #pragma unroll
            for (int i = 0; i < 3; i++)
                #pragma unroll
                for (int j = 0; j < 3; j++)
                    acc[i][j] += qr[i] * kr[j];
        }
        __syncthreads();
    }

    float tmp = temp[h];
    #pragma unroll
    for (int i = 0; i < 3; i++) {
        int dd = tr * 3 + i;
        float iq = inv[b * QK + h * D + dd];
        #pragma unroll
        for (int j = 0; j < 3; j++) {
            int ee = tc * 3 + j;
            float ik = inv[b * QK + C + h * D + ee];
            S[dd][ee] = acc[i][j] * iq * ik * tmp;
        }
    }
    __syncthreads();

    // Row softmax; one thread per row (48 active threads)
    if (tid < D) {
        float mx = -1e30f;
        #pragma unroll
        for (int e = 0; e < D; e++) mx = fmaxf(mx, S[tid][e]);
        float sum = 0.f;
        #pragma unroll
        for (int e = 0; e < D; e++) {
            float v = expf(S[tid][e] - mx);
            S[tid][e] = v;
            sum += v;
        }
        float r = 1.f / sum;
        float* arow = attn + (size_t)bh * D * D + tid * D;
        #pragma unroll
        for (int e = 0; e < D; e++) arow[e] = S[tid][e] * r;
    }
}

// ---------------------------------------------------------------------------
// out[d,n] = sum_e attn[d,e] * v[e,n]. Grid: (b*h, hw/256); 256 threads.
// Writes to g_av in (b, c, hw) layout for the proj GEMM.
// ---------------------------------------------------------------------------
__global__ __launch_bounds__(256)
void av_kernel(const float* __restrict__ dw, const float* __restrict__ attn,
               float* __restrict__ out)
{
    int bh = blockIdx.x;
    int b  = bh / NH;
    int h  = bh % NH;
    int n  = blockIdx.y * 256 + threadIdx.x;

    __shared__ float A[D][D];
    for (int l = threadIdx.x; l < D * D; l += 256)
        A[l / D][l % D] = attn[(size_t)bh * D * D + l];
    __syncthreads();

    const float* vbase = dw  + ((size_t)b * C3 + 2 * C + h * D) * HW;
    float*       obase = out + ((size_t)b * C  +         h * D) * HW;

    float v[D];
    #pragma unroll
    for (int e = 0; e < D; e++) v[e] = vbase[(size_t)e * HW + n];

    #pragma unroll
    for (int d = 0; d < D; d++) {
        float s = 0.f;
        #pragma unroll
        for (int e = 0; e < D; e++) s += A[d][e] * v[e];
        obase[(size_t)d * HW + n] = s;
    }
}

// ---------------------------------------------------------------------------
// Launch
// ---------------------------------------------------------------------------
extern "C" void kernel_launch(void* const* d_in, const int* in_sizes, int n_in,
                              void* d_out, int out_size)
{
    const float* x      = (const float*)d_in[0];   // (16,384,64,64)
    const float* w_qkv  = (const float*)d_in[1];   // (1152,384)
    const float* w_dw   = (const float*)d_in[2];   // (1152,1,3,3)
    const float* w_proj = (const float*)d_in[3];   // (384,384)
    const float* temp   = (const float*)d_in[4];   // (1,8,1,1)
    float* out = (float*)d_out;

    float *qkv, *dwb, *invb, *attnb, *avb;
    cudaGetSymbolAddress((void**)&qkv,  g_qkv);
    cudaGetSymbolAddress((void**)&dwb,  g_dw);
    cudaGetSymbolAddress((void**)&invb, g_inv);
    cudaGetSymbolAddress((void**)&attnb, g_attn);
    cudaGetSymbolAddress((void**)&avb,  g_av);

    // 1) qkv = w_qkv @ x   : M=1152, N=4096, K=384, batched over 16
    {
        dim3 grid(HW / 128, C3 / 128, BATCH);
        gemm128_kernel<<<grid, 256>>>(w_qkv, x, qkv, C3, HW, C);
    }
    // 2) depthwise 3x3
    dwconv_kernel<<<BATCH * C3, 256>>>(qkv, w_dw, dwb);
    // 3) inverse L2 norms for q,k channels
    norm_kernel<<<BATCH * QK, 256>>>(dwb, invb);
    // 4) scores + softmax
    scores_softmax_kernel<<<BATCH * NH, 256>>>(dwb, invb, temp, attnb);
    // 5) attn @ v -> (b,c,hw)
    {
        dim3 grid(BATCH * NH, HW / 256);
        av_kernel<<<grid, 256>>>(dwb, attnb, avb);
    }
    // 6) proj: M=384, N=4096, K=384, batched over 16 -> d_out
    {
        dim3 grid(HW / 128, C / 128, BATCH);
        gemm128_kernel<<<grid, 256>>>(w_proj, avb, out, C, HW, C);
    }
}

// round 3
// speedup vs baseline: 2.1062x; 2.1062x over previous
#include <cuda_runtime.h>
#include <cuda_bf16.h>
#include <cstdint>

// ---------------------------------------------------------------------------
// Problem constants
// ---------------------------------------------------------------------------
#define BATCH 16
#define C     384
#define C3    1152
#define HW    4096
#define HH    64
#define NH    8
#define D     48
#define KDIM  384
#define NSPLIT 8
#define SPN   (HW / NSPLIT)

#define SMEM_SWIZZLE_128B(byte_offset) \
    ((byte_offset) ^ (((byte_offset) >> 3) & 0x70))

__device__ __forceinline__ uint32_t smem_to_u32(const void* smem_ptr) {
    uint32_t addr;
    asm("{ .reg .u64 tmp; cvta.to.shared.u64 tmp, %1; cvt.u32.u64 %0, tmp; }"
        : "=r"(addr) : "l"(smem_ptr));
    return addr;
}

__device__ __forceinline__ void ldsm4(uint32_t& r0, uint32_t& r1,
                                      uint32_t& r2, uint32_t& r3, uint32_t addr) {
    asm volatile("ldmatrix.sync.aligned.m8n8.x4.shared.b16 {%0,%1,%2,%3}, [%4];"
                 : "=r"(r0), "=r"(r1), "=r"(r2), "=r"(r3) : "r"(addr));
}

__device__ __forceinline__ void mma16816(float* d, const uint32_t* a,
                                         uint32_t b0, uint32_t b1) {
    asm volatile(
        "mma.sync.aligned.m16n8k16.row.col.f32.bf16.bf16.f32 "
        "{%0,%1,%2,%3}, {%4,%5,%6,%7}, {%8,%9}, {%0,%1,%2,%3};"
        : "+f"(d[0]), "+f"(d[1]), "+f"(d[2]), "+f"(d[3])
        : "r"(a[0]), "r"(a[1]), "r"(a[2]), "r"(a[3]), "r"(b0), "r"(b1));
}

// ---------------------------------------------------------------------------
// Scratch (static device allocations)
// ---------------------------------------------------------------------------
__device__ float g_qkv[(size_t)BATCH * C3 * HW];                 // 302 MB
__device__ float g_dw [(size_t)BATCH * C3 * HW];                 // 302 MB
__device__ __align__(16) __nv_bfloat16 g_xT_hi[(size_t)BATCH * HW * KDIM];
__device__ __align__(16) __nv_bfloat16 g_xT_lo[(size_t)BATCH * HW * KDIM];
__device__ __align__(16) __nv_bfloat16 g_avT_hi[(size_t)BATCH * HW * KDIM];
__device__ __align__(16) __nv_bfloat16 g_avT_lo[(size_t)BATCH * HW * KDIM];
__device__ __align__(16) __nv_bfloat16 g_w1_hi[C3 * KDIM];
__device__ __align__(16) __nv_bfloat16 g_w1_lo[C3 * KDIM];
__device__ __align__(16) __nv_bfloat16 g_w2_hi[C * KDIM];
__device__ __align__(16) __nv_bfloat16 g_w2_lo[C * KDIM];
__device__ float g_part[(size_t)NSPLIT * BATCH * NH * D * D];
__device__ float g_qk2 [(size_t)NSPLIT * BATCH * NH * 96];
__device__ float g_attn[BATCH * NH * D * D];

// ---------------------------------------------------------------------------
// Elementwise fp32 -> bf16 hi/lo split
// ---------------------------------------------------------------------------
__global__ __launch_bounds__(256)
void conv_split_kernel(const float* __restrict__ src,
                       __nv_bfloat16* __restrict__ hi,
                       __nv_bfloat16* __restrict__ lo, int n)
{
    int i = blockIdx.x * 256 + threadIdx.x;
    if (i < n) {
        float v = src[i];
        __nv_bfloat16 h = __float2bfloat16(v);
        hi[i] = h;
        lo[i] = __float2bfloat16(v - __bfloat162float(h));
    }
}

// ---------------------------------------------------------------------------
// Transpose + split: x[b][c][n] fp32 -> xT_hi/lo[b][n][c] bf16
// ---------------------------------------------------------------------------
__global__ __launch_bounds__(256)
void transpose_split_kernel(const float* __restrict__ x,
                            __nv_bfloat16* __restrict__ thi,
                            __nv_bfloat16* __restrict__ tlo)
{
    int b  = blockIdx.z;
    int c0 = blockIdx.y * 32;
    int n0 = blockIdx.x * 32;
    int tx = threadIdx.x & 31;
    int ty = threadIdx.x >> 5;     // 0..7

    __shared__ float t[32][33];
    const float* xb = x + ((size_t)b * C + c0) * HW + n0;
    #pragma unroll
    for (int ii = 0; ii < 4; ii++) {
        int cc = ty + ii * 8;
        t[cc][tx] = xb[(size_t)cc * HW + tx];
    }
    __syncthreads();
    size_t obase = ((size_t)b * HW + n0) * KDIM + c0;
    #pragma unroll
    for (int ii = 0; ii < 4; ii++) {
        int nn = ty + ii * 8;
        float v = t[tx][nn];
        __nv_bfloat16 h = __float2bfloat16(v);
        thi[obase + (size_t)nn * KDIM + tx] = h;
        tlo[obase + (size_t)nn * KDIM + tx] =
            __float2bfloat16(v - __bfloat162float(h));
    }
}

// ---------------------------------------------------------------------------
// Tensor-core GEMM (mma.sync bf16, hi/lo split):
//   Cout[b] (M x 4096 fp32) = W (M x 384) @ X[b] (384 x 4096)
// W given as bf16 hi/lo row-major [M][K]; X as bf16 hi/lo transposed [n][K].
// Block 128(M) x 128(N) x K-chunks of 64; 8 warps in 2(M) x 4(N); warp 64x32.
// SMEM tiles 128 rows x 128B, SW128 swizzled for conflict-free ldmatrix.
// ---------------------------------------------------------------------------
#define SA_HI 0
#define SA_LO 16384
#define SB_HI 32768
#define SB_LO 49152
#define SM_GEMM 65536

__global__ __launch_bounds__(256)
void mma_gemm_kernel(const __nv_bfloat16* __restrict__ Whi,
                     const __nv_bfloat16* __restrict__ Wlo,
                     const __nv_bfloat16* __restrict__ XThi,
                     const __nv_bfloat16* __restrict__ XTlo,
                     float* __restrict__ Cout, int M)
{
    extern __shared__ char sm[];
    const uint32_t s_base = smem_to_u32(sm);
    const int tid  = threadIdx.x;
    const int lane = tid & 31;
    const int warp = tid >> 5;
    const int wm   = warp >> 2;      // 0..1
    const int wn   = warp & 3;       // 0..3

    const int n0 = blockIdx.x * 128;
    const int m0 = blockIdx.y * 128;
    const int b  = blockIdx.z;
    const __nv_bfloat16* XhiB = XThi + (size_t)b * HW * KDIM;
    const __nv_bfloat16* XloB = XTlo + (size_t)b * HW * KDIM;
    float* Cb = Cout + (size_t)b * M * HW;

    float acc[4][4][4];
    #pragma unroll
    for (int i = 0; i < 4; i++)
        #pragma unroll
        for (int j = 0; j < 4; j++)
            #pragma unroll
            for (int r = 0; r < 4; r++) acc[i][j][r] = 0.f;

    // ldmatrix lane-address components
    const uint32_t rx = lane & 7;                    // row&7 for swizzle XOR
    const uint32_t gA = lane >> 4;                   // 0/1 -> k granule select
    const uint32_t gB = (lane >> 3) & 1;
    uint32_t aoff[4], boff[2];
    #pragma unroll
    for (int mt = 0; mt < 4; mt++)
        aoff[mt] = (uint32_t)(wm * 64 + mt * 16 + (lane & 15)) * 128;
    #pragma unroll
    for (int ntp = 0; ntp < 2; ntp++)
        boff[ntp] = (uint32_t)(wn * 32 + ntp * 16 + (lane & 7) + ((lane >> 4) << 3)) * 128;

    for (int kc = 0; kc < KDIM / 64; kc++) {
        const int k0 = kc * 64;
        __syncthreads();
        // stage 4 tiles: 128 rows x 64 bf16 (128B) each, swizzled
        #pragma unroll
        for (int l = tid; l < 1024; l += 256) {
            int r = l >> 3, g = l & 7;
            uint32_t so = SMEM_SWIZZLE_128B((uint32_t)(r * 128 + g * 16));
            size_t wg = (size_t)(m0 + r) * KDIM + k0 + g * 8;
            size_t xg = (size_t)(n0 + r) * KDIM + k0 + g * 8;
            *(uint4*)(sm + SA_HI + so) = *(const uint4*)(Whi + wg);
            *(uint4*)(sm + SA_LO + so) = *(const uint4*)(Wlo + wg);
            *(uint4*)(sm + SB_HI + so) = *(const uint4*)(XhiB + xg);
            *(uint4*)(sm + SB_LO + so) = *(const uint4*)(XloB + xg);
        }
        __syncthreads();

        #pragma unroll
        for (int ks = 0; ks < 4; ks++) {
            uint32_t ahi[4][4], alo[4][4];
            #pragma unroll
            for (int mt = 0; mt < 4; mt++) {
                uint32_t off = aoff[mt] + ((((uint32_t)(ks << 1) + gA) ^ rx) << 4);
                ldsm4(ahi[mt][0], ahi[mt][1], ahi[mt][2], ahi[mt][3],
                      s_base + SA_HI + off);
                ldsm4(alo[mt][0], alo[mt][1], alo[mt][2], alo[mt][3],
                      s_base + SA_LO + off);
            }
            #pragma unroll
            for (int ntp = 0; ntp < 2; ntp++) {
                uint32_t off = boff[ntp] + ((((uint32_t)(ks << 1) + gB) ^ rx) << 4);
                uint32_t bh[4], bl[4];
                ldsm4(bh[0], bh[1], bh[2], bh[3], s_base + SB_HI + off);
                ldsm4(bl[0], bl[1], bl[2], bl[3], s_base + SB_LO + off);
                #pragma unroll
                for (int mt = 0; mt < 4; mt++) {
                    #pragma unroll
                    for (int h2 = 0; h2 < 2; h2++) {
                        float* dacc = acc[mt][ntp * 2 + h2];
                        mma16816(dacc, ahi[mt], bh[h2 * 2], bh[h2 * 2 + 1]);
                        mma16816(dacc, ahi[mt], bl[h2 * 2], bl[h2 * 2 + 1]);
                        mma16816(dacc, alo[mt], bh[h2 * 2], bh[h2 * 2 + 1]);
                    }
                }
            }
        }
    }

    // epilogue
    const int g = lane >> 2, q = lane & 3;
    #pragma unroll
    for (int mt = 0; mt < 4; mt++) {
        #pragma unroll
        for (int nt = 0; nt < 4; nt++) {
            size_t row = (size_t)(m0 + wm * 64 + mt * 16 + g);
            size_t col = (size_t)(n0 + wn * 32 + nt * 8 + q * 2);
            float2 v0 = make_float2(acc[mt][nt][0], acc[mt][nt][1]);
            float2 v1 = make_float2(acc[mt][nt][2], acc[mt][nt][3]);
            *(float2*)(Cb + row * HW + col)       = v0;
            *(float2*)(Cb + (row + 8) * HW + col) = v1;
        }
    }
}

// ---------------------------------------------------------------------------
// Depthwise 3x3 conv, SAME padding. One block per (b, channel) plane.
// ---------------------------------------------------------------------------
__global__ __launch_bounds__(256)
void dwconv_kernel(const float* __restrict__ in, const float* __restrict__ wdw,
                   float* __restrict__ out)
{
    int plane = blockIdx.x;
    int ch    = plane % C3;
    const float* ip = in  + (size_t)plane * HW;
    float*       op = out + (size_t)plane * HW;

    __shared__ float tile[66][66];
    for (int l = threadIdx.x; l < 66 * 66; l += 256) {
        int y = l / 66 - 1, x = l % 66 - 1;
        tile[l / 66][l % 66] =
            (y >= 0 && y < HH && x >= 0 && x < HH) ? ip[y * HH + x] : 0.f;
    }
    __syncthreads();

    float w[9];
    #pragma unroll
    for (int i = 0; i < 9; i++) w[i] = wdw[ch * 9 + i];

    for (int l = threadIdx.x; l < HW; l += 256) {
        int y = l >> 6, x = l & 63;
        float s = 0.f;
        #pragma unroll
        for (int dy = 0; dy < 3; dy++)
            #pragma unroll
            for (int dx = 0; dx < 3; dx++)
                s += w[dy * 3 + dx] * tile[y + dy][x + dx];
        op[l] = s;
    }
}

// ---------------------------------------------------------------------------
// Scores split-K partials + folded norm partial sums.
// ---------------------------------------------------------------------------
__global__ __launch_bounds__(256)
void scores_partial_kernel(const float* __restrict__ dw,
                           float* __restrict__ part, float* __restrict__ qk2)
{
    int bh = blockIdx.x, sp = blockIdx.y;
    int b = bh / NH, h = bh % NH;
    const float* qbase = dw + ((size_t)b * C3 +     h * D) * HW + sp * SPN;
    const float* kbase = dw + ((size_t)b * C3 + C + h * D) * HW + sp * SPN;

    __shared__ float qs[D][65];
    __shared__ float ks[D][65];

    int tid = threadIdx.x;
    int tr  = tid / 16;
    int tc  = tid % 16;

    float acc[3][3];
    #pragma unroll
    for (int i = 0; i < 3; i++)
        #pragma unroll
        for (int j = 0; j < 3; j++) acc[i][j] = 0.f;
    float nrm = 0.f;

    for (int n0 = 0; n0 < SPN; n0 += 64) {
        for (int l = tid; l < D * 64; l += 256) {
            int r = l >> 6, c = l & 63;
            qs[r][c] = qbase[(size_t)r * HW + n0 + c];
            ks[r][c] = kbase[(size_t)r * HW + n0 + c];
        }
        __syncthreads();
        #pragma unroll 8
        for (int n = 0; n < 64; n++) {
            float qr[3], kr[3];
            #pragma unroll
            for (int i = 0; i < 3; i++) qr[i] = qs[tr * 3 + i][n];
            #pragma unroll
            for (int j = 0; j < 3; j++) kr[j] = ks[tc * 3 + j][n];
            #pragma unroll
            for (int i = 0; i < 3; i++)
                #pragma unroll
                for (int j = 0; j < 3; j++)
                    acc[i][j] += qr[i] * kr[j];
        }
        if (tid < 96) {
            int r = (tid < 48) ? tid : tid - 48;
            const float (*src)[65] = (tid < 48) ? qs : ks;
            #pragma unroll 8
            for (int cidx = 0; cidx < 64; cidx++) {
                float v = src[r][cidx];
                nrm += v * v;
            }
        }
        __syncthreads();
    }

    float* pp = part + ((size_t)sp * (BATCH * NH) + bh) * (D * D);
    #pragma unroll
    for (int i = 0; i < 3; i++)
        #pragma unroll
        for (int j = 0; j < 3; j++)
            pp[(tr * 3 + i) * D + tc * 3 + j] = acc[i][j];
    if (tid < 96)
        qk2[((size_t)sp * (BATCH * NH) + bh) * 96 + tid] = nrm;
}

// ---------------------------------------------------------------------------
// Reduce partials, folded norms + temperature, softmax -> attn.
// ---------------------------------------------------------------------------
__global__ __launch_bounds__(256)
void scores_finalize_kernel(const float* __restrict__ part,
                            const float* __restrict__ qk2,
                            const float* __restrict__ temp,
                            float* __restrict__ attn)
{
    int bh = blockIdx.x;
    int h  = bh % NH;
    int tid = threadIdx.x;

    __shared__ float S[D][D + 1];
    __shared__ float invn[96];

    if (tid < 96) {
        float s = 0.f;
        #pragma unroll
        for (int sp = 0; sp < NSPLIT; sp++)
            s += qk2[((size_t)sp * (BATCH * NH) + bh) * 96 + tid];
        invn[tid] = 1.f / fmaxf(sqrtf(s), 1e-12f);
    }
    __syncthreads();

    float tmp = temp[h];
    for (int l = tid; l < D * D; l += 256) {
        float s = 0.f;
        #pragma unroll
        for (int sp = 0; sp < NSPLIT; sp++)
            s += part[((size_t)sp * (BATCH * NH) + bh) * (D * D) + l];
        int dd = l / D, ee = l % D;
        S[dd][ee] = s * invn[dd] * invn[48 + ee] * tmp;
    }
    __syncthreads();

    if (tid < D) {
        float mx = -1e30f;
        #pragma unroll
        for (int e = 0; e < D; e++) mx = fmaxf(mx, S[tid][e]);
        float sum = 0.f;
        #pragma unroll
        for (int e = 0; e < D; e++) {
            float v = expf(S[tid][e] - mx);
            S[tid][e] = v;
            sum += v;
        }
        float r = 1.f / sum;
        float* arow = attn + (size_t)bh * D * D + tid * D;
        #pragma unroll
        for (int e = 0; e < D; e++) arow[e] = S[tid][e] * r;
    }
}

// ---------------------------------------------------------------------------
// out[d,n] = sum_e attn[d,e] * v[e,n]; emit transposed bf16 hi/lo [b][n][c]
// ---------------------------------------------------------------------------
__global__ __launch_bounds__(256)
void av_kernel(const float* __restrict__ dw, const float* __restrict__ attn,
               __nv_bfloat16* __restrict__ avhi, __nv_bfloat16* __restrict__ avlo)
{
    int bh = blockIdx.x;
    int b  = bh / NH;
    int h  = bh % NH;
    int n  = blockIdx.y * 256 + threadIdx.x;

    __shared__ float A[D][D];
    for (int l = threadIdx.x; l < D * D; l += 256)
        A[l / D][l % D] = attn[(size_t)bh * D * D + l];
    __syncthreads();

    const float* vbase = dw + ((size_t)b * C3 + 2 * C + h * D) * HW;
    size_t obase = ((size_t)b * HW + n) * KDIM + h * D;

    float v[D];
    #pragma unroll
    for (int e = 0; e < D; e++) v[e] = vbase[(size_t)e * HW + n];

    #pragma unroll
    for (int d2 = 0; d2 < D; d2++) {
        float s = 0.f;
        #pragma unroll
        for (int e = 0; e < D; e++) s += A[d2][e] * v[e];
        __nv_bfloat16 hh = __float2bfloat16(s);
        avhi[obase + d2] = hh;
        avlo[obase + d2] = __float2bfloat16(s - __bfloat162float(hh));
    }
}

// ---------------------------------------------------------------------------
// Launch
// ---------------------------------------------------------------------------
extern "C" void kernel_launch(void* const* d_in, const int* in_sizes, int n_in,
                              void* d_out, int out_size)
{
    const float* x      = (const float*)d_in[0];
    const float* w_qkv  = (const float*)d_in[1];
    const float* w_dw   = (const float*)d_in[2];
    const float* w_proj = (const float*)d_in[3];
    const float* temp   = (const float*)d_in[4];
    float* out = (float*)d_out;

    float *qkv, *dwb, *partb, *qk2b, *attnb;
    __nv_bfloat16 *xThi, *xTlo, *avhi, *avlo, *w1hi, *w1lo, *w2hi, *w2lo;
    cudaGetSymbolAddress((void**)&qkv,   g_qkv);
    cudaGetSymbolAddress((void**)&dwb,   g_dw);
    cudaGetSymbolAddress((void**)&partb, g_part);
    cudaGetSymbolAddress((void**)&qk2b,  g_qk2);
    cudaGetSymbolAddress((void**)&attnb, g_attn);
    cudaGetSymbolAddress((void**)&xThi,  g_xT_hi);
    cudaGetSymbolAddress((void**)&xTlo,  g_xT_lo);
    cudaGetSymbolAddress((void**)&avhi,  g_avT_hi);
    cudaGetSymbolAddress((void**)&avlo,  g_avT_lo);
    cudaGetSymbolAddress((void**)&w1hi,  g_w1_hi);
    cudaGetSymbolAddress((void**)&w1lo,  g_w1_lo);
    cudaGetSymbolAddress((void**)&w2hi,  g_w2_hi);
    cudaGetSymbolAddress((void**)&w2lo,  g_w2_lo);

    static bool attr_set = false;
    if (!attr_set) {
        cudaFuncSetAttribute(mma_gemm_kernel,
                             cudaFuncAttributeMaxDynamicSharedMemorySize, SM_GEMM);
        attr_set = true;
    }

    // 0) conversions
    conv_split_kernel<<<(C3 * KDIM + 255) / 256, 256>>>(w_qkv, w1hi, w1lo, C3 * KDIM);
    conv_split_kernel<<<(C * KDIM + 255) / 256, 256>>>(w_proj, w2hi, w2lo, C * KDIM);
    transpose_split_kernel<<<dim3(HW / 32, C / 32, BATCH), 256>>>(x, xThi, xTlo);
    // 1) qkv = w_qkv @ x  (tensor cores)
    mma_gemm_kernel<<<dim3(HW / 128, C3 / 128, BATCH), 256, SM_GEMM>>>(
        w1hi, w1lo, xThi, xTlo, qkv, C3);
    // 2) depthwise 3x3
    dwconv_kernel<<<BATCH * C3, 256>>>(qkv, w_dw, dwb);
    // 3) scores partials (split-K + folded norms)
    scores_partial_kernel<<<dim3(BATCH * NH, NSPLIT), 256>>>(dwb, partb, qk2b);
    // 4) reduce + softmax
    scores_finalize_kernel<<<BATCH * NH, 256>>>(partb, qk2b, temp, attnb);
    // 5) attn @ v -> transposed bf16 split
    av_kernel<<<dim3(BATCH * NH, HW / 256), 256>>>(dwb, attnb, avhi, avlo);
    // 6) proj (tensor cores) -> d_out
    mma_gemm_kernel<<<dim3(HW / 128, C / 128, BATCH), 256, SM_GEMM>>>(
        w2hi, w2lo, avhi, avlo, out, C);
}

// round 6
// speedup vs baseline: 4.2293x; 2.0081x over previous
#include <cuda_runtime.h>
#include <cuda_fp16.h>
#include <cstdint>

// ---------------------------------------------------------------------------
// Problem constants
// ---------------------------------------------------------------------------
#define BATCH 16
#define C     384
#define C3    1152
#define HW    4096
#define HH    64
#define NH    8
#define D     48
#define KDIM  384
#define QK    768
#define NSPLIT 8
#define SPN   (HW / NSPLIT)
#define NC    (KDIM / 64)     // 6 k-chunks

#define SMEM_SWIZZLE_128B(byte_offset) \
    ((byte_offset) ^ (((byte_offset) >> 3) & 0x70))

__device__ __forceinline__ uint32_t smem_to_u32(const void* smem_ptr) {
    uint32_t addr;
    asm("{ .reg .u64 tmp; cvta.to.shared.u64 tmp, %1; cvt.u32.u64 %0, tmp; }"
        : "=r"(addr) : "l"(smem_ptr));
    return addr;
}

__device__ __forceinline__ void ldsm4(uint32_t& r0, uint32_t& r1,
                                      uint32_t& r2, uint32_t& r3, uint32_t addr) {
    asm volatile("ldmatrix.sync.aligned.m8n8.x4.shared.b16 {%0,%1,%2,%3}, [%4];"
                 : "=r"(r0), "=r"(r1), "=r"(r2), "=r"(r3) : "r"(addr));
}

__device__ __forceinline__ void mma16816(float* d, const uint32_t* a,
                                         uint32_t b0, uint32_t b1) {
    asm volatile(
        "mma.sync.aligned.m16n8k16.row.col.f32.f16.f16.f32 "
        "{%0,%1,%2,%3}, {%4,%5,%6,%7}, {%8,%9}, {%0,%1,%2,%3};"
        : "+f"(d[0]), "+f"(d[1]), "+f"(d[2]), "+f"(d[3])
        : "r"(a[0]), "r"(a[1]), "r"(a[2]), "r"(a[3]), "r"(b0), "r"(b1));
}

__device__ __forceinline__ void cp_async16(uint32_t saddr, const void* gaddr) {
    asm volatile("cp.async.cg.shared.global [%0], [%1], 16;"
                 :: "r"(saddr), "l"(gaddr));
}
#define CP_COMMIT() asm volatile("cp.async.commit_group;" ::: "memory")
template <int N>
__device__ __forceinline__ void cp_wait() {
    asm volatile("cp.async.wait_group %0;" :: "n"(N) : "memory");
}

// epilogue store helpers
__device__ __forceinline__ void store2(float* p, float a, float b) {
    *(float2*)p = make_float2(a, b);
}
__device__ __forceinline__ void store2(__half* p, float a, float b) {
    *(__half2*)p = __floats2half2_rn(a, b);
}

// ---------------------------------------------------------------------------
// Scratch
// ---------------------------------------------------------------------------
__device__ __align__(16) __half g_qkv[(size_t)BATCH * C3 * HW];   // fp16 GEMM out
__device__ float g_dw [(size_t)BATCH * C3 * HW];                  // dwconv out fp32
__device__ __align__(16) __half g_xT [(size_t)BATCH * HW * KDIM]; // x transposed fp16
__device__ __align__(16) __half g_avT[(size_t)BATCH * HW * KDIM]; // av transposed fp16
__device__ __align__(16) __half g_w1 [C3 * KDIM];
__device__ __align__(16) __half g_w2 [C * KDIM];
__device__ float g_norm[BATCH * QK];                              // per-channel sum(v^2)
__device__ float g_part[(size_t)NSPLIT * BATCH * NH * D * D];
__device__ float g_attn[BATCH * NH * D * D];

// ---------------------------------------------------------------------------
// fp32 -> fp16 weight conversion
// ---------------------------------------------------------------------------
__global__ __launch_bounds__(256)
void convw_kernel(const float* __restrict__ src, __half* __restrict__ dst, int n)
{
    int i = blockIdx.x * 256 + threadIdx.x;
    if (i < n) dst[i] = __float2half_rn(src[i]);
}

// ---------------------------------------------------------------------------
// Transpose: x[b][c][n] fp32 -> xT[b][n][c] fp16
// ---------------------------------------------------------------------------
__global__ __launch_bounds__(256)
void transpose_kernel(const float* __restrict__ x, __half* __restrict__ xt)
{
    int b  = blockIdx.z;
    int c0 = blockIdx.y * 32;
    int n0 = blockIdx.x * 32;
    int tx = threadIdx.x & 31;
    int ty = threadIdx.x >> 5;

    __shared__ float t[32][33];
    const float* xb = x + ((size_t)b * C + c0) * HW + n0;
    #pragma unroll
    for (int ii = 0; ii < 4; ii++) {
        int cc = ty + ii * 8;
        t[cc][tx] = xb[(size_t)cc * HW + tx];
    }
    __syncthreads();
    size_t obase = ((size_t)b * HW + n0) * KDIM + c0;
    #pragma unroll
    for (int ii = 0; ii < 4; ii++) {
        int nn = ty + ii * 8;
        xt[obase + (size_t)nn * KDIM + tx] = __float2half_rn(t[tx][nn]);
    }
}

// ---------------------------------------------------------------------------
// fp16 tensor-core GEMM, cp.async double-buffered:
//   Cout[b] (M x 4096) = W (M x 384) @ X[b] (384 x 4096)
// W fp16 row-major [M][K]; X fp16 transposed [b][n][K]. Out fp32 or fp16.
// Block 128x128xK64; 8 warps (2x4); warp 64x32. SW128-swizzled SMEM.
// ---------------------------------------------------------------------------
#define SM_BUF 32768           // per-stage: A 16KB + B 16KB
#define SM_GEMM (2 * SM_BUF)   // 64 KB

template <typename OutT>
__global__ __launch_bounds__(256)
void mma_gemm_fp16(const __half* __restrict__ Wg, const __half* __restrict__ XT,
                   OutT* __restrict__ Cout, int M)
{
    extern __shared__ char sm[];
    const uint32_t s_base = smem_to_u32(sm);
    const int tid  = threadIdx.x;
    const int lane = tid & 31;
    const int warp = tid >> 5;
    const int wm   = warp >> 2;
    const int wn   = warp & 3;

    const int n0 = blockIdx.x * 128;
    const int m0 = blockIdx.y * 128;
    const int b  = blockIdx.z;
    const __half* Xb = XT + (size_t)b * HW * KDIM;
    OutT* Cb = Cout + (size_t)b * M * HW;

    // per-thread staging map (4 x 16B granules per tile)
    int srow[4], sgrn[4];
    uint32_t soff[4];
    #pragma unroll
    for (int i = 0; i < 4; i++) {
        int l = tid + i * 256;
        srow[i] = l >> 3;
        sgrn[i] = l & 7;
        soff[i] = SMEM_SWIZZLE_128B((uint32_t)(srow[i] * 128 + sgrn[i] * 16));
    }

    auto stage = [&](int buf, int kc) {
        const int k0 = kc * 64;
        uint32_t abase = s_base + buf * SM_BUF;
        uint32_t bbase = abase + 16384;
        #pragma unroll
        for (int i = 0; i < 4; i++) {
            cp_async16(abase + soff[i],
                       Wg + (size_t)(m0 + srow[i]) * KDIM + k0 + sgrn[i] * 8);
            cp_async16(bbase + soff[i],
                       Xb + (size_t)(n0 + srow[i]) * KDIM + k0 + sgrn[i] * 8);
        }
    };

    float acc[4][4][4];
    #pragma unroll
    for (int i = 0; i < 4; i++)
        #pragma unroll
        for (int j = 0; j < 4; j++)
            #pragma unroll
            for (int r = 0; r < 4; r++) acc[i][j][r] = 0.f;

    const uint32_t rx = lane & 7;
    const uint32_t gA = lane >> 4;
    const uint32_t gB = (lane >> 3) & 1;
    uint32_t aoff[4], boff[2];
    #pragma unroll
    for (int mt = 0; mt < 4; mt++)
        aoff[mt] = (uint32_t)(wm * 64 + mt * 16 + (lane & 15)) * 128;
    #pragma unroll
    for (int ntp = 0; ntp < 2; ntp++)
        boff[ntp] = (uint32_t)(wn * 32 + ntp * 16 + (lane & 7) + ((lane >> 4) << 3)) * 128;

    stage(0, 0);
    CP_COMMIT();

    for (int kc = 0; kc < NC; kc++) {
        if (kc + 1 < NC) {
            stage((kc + 1) & 1, kc + 1);
            CP_COMMIT();
            cp_wait<1>();
        } else {
            cp_wait<0>();
        }
        __syncthreads();

        uint32_t abase = s_base + (kc & 1) * SM_BUF;
        uint32_t bbase = abase + 16384;
        #pragma unroll
        for (int ks = 0; ks < 4; ks++) {
            uint32_t a[4][4];
            #pragma unroll
            for (int mt = 0; mt < 4; mt++) {
                uint32_t off = aoff[mt] + ((((uint32_t)(ks << 1) + gA) ^ rx) << 4);
                ldsm4(a[mt][0], a[mt][1], a[mt][2], a[mt][3], abase + off);
            }
            #pragma unroll
            for (int ntp = 0; ntp < 2; ntp++) {
                uint32_t off = boff[ntp] + ((((uint32_t)(ks << 1) + gB) ^ rx) << 4);
                uint32_t bh[4];
                ldsm4(bh[0], bh[1], bh[2], bh[3], bbase + off);
                #pragma unroll
                for (int mt = 0; mt < 4; mt++) {
                    #pragma unroll
                    for (int h2 = 0; h2 < 2; h2++)
                        mma16816(acc[mt][ntp * 2 + h2], a[mt],
                                 bh[h2 * 2], bh[h2 * 2 + 1]);
                }
            }
        }
        __syncthreads();
    }

    // epilogue
    const int g = lane >> 2, q = lane & 3;
    #pragma unroll
    for (int mt = 0; mt < 4; mt++) {
        #pragma unroll
        for (int nt = 0; nt < 4; nt++) {
            size_t row = (size_t)(m0 + wm * 64 + mt * 16 + g);
            size_t col = (size_t)(n0 + wn * 32 + nt * 8 + q * 2);
            store2(Cb + row * HW + col,       acc[mt][nt][0], acc[mt][nt][1]);
            store2(Cb + (row + 8) * HW + col, acc[mt][nt][2], acc[mt][nt][3]);
        }
    }
}

// ---------------------------------------------------------------------------
// Depthwise 3x3 conv (half in, float out), SAME padding, one block per plane.
// Halo is all-zero (block covers the full 64x64 plane). Also reduces the
// per-channel sum of squares for q,k channels (ch < 768) into g_norm.
// ---------------------------------------------------------------------------
__global__ __launch_bounds__(256)
void dwconv_kernel(const __half* __restrict__ in, const float* __restrict__ wdw,
                   float* __restrict__ out, float* __restrict__ norm)
{
    int plane = blockIdx.x;
    int ch    = plane % C3;
    int b     = plane / C3;
    const __half* ip = in  + (size_t)plane * HW;
    float*        op = out + (size_t)plane * HW;

    __shared__ float tile[66][66];
    // zero borders
    for (int l = threadIdx.x; l < 66; l += 256) {
        tile[0][l] = 0.f;
        tile[65][l] = 0.f;
        tile[l][0] = 0.f;
        tile[l][65] = 0.f;
    }
    // interior via half2 (row = 64 halfs = aligned 128B)
    for (int l = threadIdx.x; l < HH * 32; l += 256) {
        int y = l >> 5, px = l & 31;
        __half2 v = *(const __half2*)(ip + y * HH + px * 2);
        float2 f = __half22float2(v);
        tile[y + 1][px * 2 + 1] = f.x;
        tile[y + 1][px * 2 + 2] = f.y;
    }
    __syncthreads();

    float w[9];
    #pragma unroll
    for (int i = 0; i < 9; i++) w[i] = wdw[ch * 9 + i];

    float nrm = 0.f;
    for (int l = threadIdx.x; l < HW; l += 256) {
        int y = l >> 6, x = l & 63;
        float s = 0.f;
        #pragma unroll
        for (int dy = 0; dy < 3; dy++)
            #pragma unroll
            for (int dx = 0; dx < 3; dx++)
                s += w[dy * 3 + dx] * tile[y + dy][x + dx];
        op[l] = s;
        nrm += s * s;
    }

    if (ch < QK) {
        #pragma unroll
        for (int o = 16; o > 0; o >>= 1)
            nrm += __shfl_down_sync(0xffffffffu, nrm, o);
        __shared__ float ws[8];
        if ((threadIdx.x & 31) == 0) ws[threadIdx.x >> 5] = nrm;
        __syncthreads();
        if (threadIdx.x == 0) {
            float t = 0.f;
            #pragma unroll
            for (int k = 0; k < 8; k++) t += ws[k];
            norm[b * QK + ch] = t;
        }
    }
}

// ---------------------------------------------------------------------------
// Scores split-K partials (48x48 partial Gram over 512 positions).
// ---------------------------------------------------------------------------
__global__ __launch_bounds__(256)
void scores_partial_kernel(const float* __restrict__ dw, float* __restrict__ part)
{
    int bh = blockIdx.x, sp = blockIdx.y;
    int b = bh / NH, h = bh % NH;
    const float* qbase = dw + ((size_t)b * C3 +     h * D) * HW + sp * SPN;
    const float* kbase = dw + ((size_t)b * C3 + C + h * D) * HW + sp * SPN;

    __shared__ float qs[D][65];
    __shared__ float ks[D][65];

    int tid = threadIdx.x;
    int tr  = tid / 16;
    int tc  = tid % 16;

    float acc[3][3];
    #pragma unroll
    for (int i = 0; i < 3; i++)
        #pragma unroll
        for (int j = 0; j < 3; j++) acc[i][j] = 0.f;

    for (int n0 = 0; n0 < SPN; n0 += 64) {
        for (int l = tid; l < D * 64; l += 256) {
            int r = l >> 6, c = l & 63;
            qs[r][c] = qbase[(size_t)r * HW + n0 + c];
            ks[r][c] = kbase[(size_t)r * HW + n0 + c];
        }
        __syncthreads();
        #pragma unroll 8
        for (int n = 0; n < 64; n++) {
            float qr[3], kr[3];
            #pragma unroll
            for (int i = 0; i < 3; i++) qr[i] = qs[tr * 3 + i][n];
            #pragma unroll
            for (int j = 0; j < 3; j++) kr[j] = ks[tc * 3 + j][n];
            #pragma unroll
            for (int i = 0; i < 3; i++)
                #pragma unroll
                for (int j = 0; j < 3; j++)
                    acc[i][j] += qr[i] * kr[j];
        }
        __syncthreads();
    }

    float* pp = part + ((size_t)sp * (BATCH * NH) + bh) * (D * D);
    #pragma unroll
    for (int i = 0; i < 3; i++)
        #pragma unroll
        for (int j = 0; j < 3; j++)
            pp[(tr * 3 + i) * D + tc * 3 + j] = acc[i][j];
}

// ---------------------------------------------------------------------------
// Reduce partials, folded norms + temperature, softmax -> attn.
// ---------------------------------------------------------------------------
__global__ __launch_bounds__(256)
void scores_finalize_kernel(const float* __restrict__ part,
                            const float* __restrict__ norm,
                            const float* __restrict__ temp,
                            float* __restrict__ attn)
{
    int bh = blockIdx.x;
    int b  = bh / NH;
    int h  = bh % NH;
    int tid = threadIdx.x;

    __shared__ float S[D][D + 1];
    __shared__ float invn[96];

    if (tid < 96) {
        int ch = (tid < 48) ? (h * D + tid) : (C + h * D + (tid - 48));
        float s = norm[b * QK + ch];
        invn[tid] = 1.f / fmaxf(sqrtf(s), 1e-12f);
    }
    __syncthreads();

    float tmp = temp[h];
    for (int l = tid; l < D * D; l += 256) {
        float s = 0.f;
        #pragma unroll
        for (int sp = 0; sp < NSPLIT; sp++)
            s += part[((size_t)sp * (BATCH * NH) + bh) * (D * D) + l];
        int dd = l / D, ee = l % D;
        S[dd][ee] = s * invn[dd] * invn[48 + ee] * tmp;
    }
    __syncthreads();

    if (tid < D) {
        float mx = -1e30f;
        #pragma unroll
        for (int e = 0; e < D; e++) mx = fmaxf(mx, S[tid][e]);
        float sum = 0.f;
        #pragma unroll
        for (int e = 0; e < D; e++) {
            float v = expf(S[tid][e] - mx);
            S[tid][e] = v;
            sum += v;
        }
        float r = 1.f / sum;
        float* arow = attn + (size_t)bh * D * D + tid * D;
        #pragma unroll
        for (int e = 0; e < D; e++) arow[e] = S[tid][e] * r;
    }
}

// ---------------------------------------------------------------------------
// out[d,n] = sum_e attn[d,e] * v[e,n]; emit fp16 transposed [b][n][c]
// ---------------------------------------------------------------------------
__global__ __launch_bounds__(256)
void av_kernel(const float* __restrict__ dw, const float* __restrict__ attn,
               __half* __restrict__ avT)
{
    int bh = blockIdx.x;
    int b  = bh / NH;
    int h  = bh % NH;
    int n  = blockIdx.y * 256 + threadIdx.x;

    __shared__ float A[D][D];
    for (int l = threadIdx.x; l < D * D; l += 256)
        A[l / D][l % D] = attn[(size_t)bh * D * D + l];
    __syncthreads();

    const float* vbase = dw + ((size_t)b * C3 + 2 * C + h * D) * HW;
    __half* obase = avT + ((size_t)b * HW + n) * KDIM + h * D;

    float v[D];
    #pragma unroll
    for (int e = 0; e < D; e++) v[e] = vbase[(size_t)e * HW + n];

    #pragma unroll
    for (int d2 = 0; d2 < D; d2 += 2) {
        float s0 = 0.f, s1 = 0.f;
        #pragma unroll
        for (int e = 0; e < D; e++) {
            s0 += A[d2][e] * v[e];
            s1 += A[d2 + 1][e] * v[e];
        }
        *(__half2*)(obase + d2) = __floats2half2_rn(s0, s1);
    }
}

// ---------------------------------------------------------------------------
// Launch
// ---------------------------------------------------------------------------
extern "C" void kernel_launch(void* const* d_in, const int* in_sizes, int n_in,
                              void* d_out, int out_size)
{
    const float* x      = (const float*)d_in[0];
    const float* w_qkv  = (const float*)d_in[1];
    const float* w_dw   = (const float*)d_in[2];
    const float* w_proj = (const float*)d_in[3];
    const float* temp   = (const float*)d_in[4];
    float* out = (float*)d_out;

    float *dwb, *partb, *attnb, *normb;
    __half *qkv, *xT, *avT, *w1, *w2;
    cudaGetSymbolAddress((void**)&qkv,   g_qkv);
    cudaGetSymbolAddress((void**)&dwb,   g_dw);
    cudaGetSymbolAddress((void**)&partb, g_part);
    cudaGetSymbolAddress((void**)&attnb, g_attn);
    cudaGetSymbolAddress((void**)&normb, g_norm);
    cudaGetSymbolAddress((void**)&xT,    g_xT);
    cudaGetSymbolAddress((void**)&avT,   g_avT);
    cudaGetSymbolAddress((void**)&w1,    g_w1);
    cudaGetSymbolAddress((void**)&w2,    g_w2);

    // No static guards (harness rule): set attributes unconditionally.
    cudaFuncSetAttribute(mma_gemm_fp16<__half>,
                         cudaFuncAttributeMaxDynamicSharedMemorySize, SM_GEMM);
    cudaFuncSetAttribute(mma_gemm_fp16<float>,
                         cudaFuncAttributeMaxDynamicSharedMemorySize, SM_GEMM);

    // 0) conversions
    convw_kernel<<<(C3 * KDIM + 255) / 256, 256>>>(w_qkv, w1, C3 * KDIM);
    convw_kernel<<<(C * KDIM + 255) / 256, 256>>>(w_proj, w2, C * KDIM);
    transpose_kernel<<<dim3(HW / 32, C / 32, BATCH), 256>>>(x, xT);
    // 1) qkv = w_qkv @ x  (fp16 tensor cores, fp16 out)
    mma_gemm_fp16<__half><<<dim3(HW / 128, C3 / 128, BATCH), 256, SM_GEMM>>>(
        w1, xT, qkv, C3);
    // 2) depthwise 3x3 (+ folded channel norms)
    dwconv_kernel<<<BATCH * C3, 256>>>(qkv, w_dw, dwb, normb);
    // 3) scores partials (split-K)
    scores_partial_kernel<<<dim3(BATCH * NH, NSPLIT), 256>>>(dwb, partb);
    // 4) reduce + softmax
    scores_finalize_kernel<<<BATCH * NH, 256>>>(partb, normb, temp, attnb);
    // 5) attn @ v -> fp16 transposed
    av_kernel<<<dim3(BATCH * NH, HW / 256), 256>>>(dwb, attnb, avT);
    // 6) proj (fp16 tensor cores, fp32 out) -> d_out
    mma_gemm_fp16<float><<<dim3(HW / 128, C / 128, BATCH), 256, SM_GEMM>>>(
        w2, avT, out, C);
}